// round 1
// baseline (speedup 1.0000x reference)
#include <cuda_runtime.h>
#include <cstdint>

// Physics video: 64 steps of diffusion-advection on 1024x1024 periodic grid.
// frames[t] = (r, g, b) where r = u_{t+1} (exactly, since clipped to [0,1]),
// so step t+1 reads the r channel of frame t. No scratch state needed.

#define HH 1024
#define WW 1024
#define HW (HH * WW)

// Compile-time constants from the reference
#define DT     0.1f
#define ALPHA  0.05f
#define V_X    0.1f
// V_Y == 0.0 -> du_dy term drops out.

__global__ __launch_bounds__(256) void physics_step_kernel(
    const float* __restrict__ u,      // [H, W] current state (r channel of prev frame or init)
    float* __restrict__ frame)        // [3, H, W] output frame
{
    const int tid = blockIdx.x * blockDim.x + threadIdx.x;   // 0 .. HW/4-1
    const int row = tid >> 8;          // 256 float4 per row
    const int c4  = tid & 255;
    const int x0  = c4 << 2;

    const float4* __restrict__ u4 = (const float4*)u;

    const int rowBase4 = row << 8;
    const float4 c  = u4[rowBase4 + c4];
    const float4 up = u4[(((row - 1) & (HH - 1)) << 8) + c4];
    const float4 dn = u4[(((row + 1) & (HH - 1)) << 8) + c4];

    const int rowBase = row << 10;
    const float lft = u[rowBase + ((x0 - 1) & (WW - 1))];
    const float rgt = u[rowBase + ((x0 + 4) & (WW - 1))];

    // lane-wise left/right neighbors
    float uc[4] = {c.x, c.y, c.z, c.w};
    float ul[4] = {lft, c.x, c.y, c.z};
    float ur[4] = {c.y, c.z, c.w, rgt};
    float uu[4] = {up.x, up.y, up.z, up.w};
    float ud[4] = {dn.x, dn.y, dn.z, dn.w};

    float4 rch, gch, bch;
    float* rp = &rch.x;
    float* gp = &gch.x;
    float* bp = &bch.x;

    #pragma unroll
    for (int i = 0; i < 4; ++i) {
        const float lap   = ul[i] + ur[i] + uu[i] + ud[i] - 4.0f * uc[i];
        const float du_dx = uc[i] - ul[i];
        float un = uc[i] + DT * (ALPHA * lap - V_X * du_dx);
        un = fminf(fmaxf(un, 0.0f), 1.0f);
        rp[i] = un;                                   // already in [0,1]
        gp[i] = fminf(fmaxf(un * 0.5f, 0.0f), 1.0f);
        bp[i] = fminf(fmaxf(1.0f - un, 0.0f), 1.0f);
    }

    float4* __restrict__ f4 = (float4*)frame;
    const int idx4 = rowBase4 + c4;
    f4[idx4]                = rch;   // r channel
    f4[idx4 + (HW / 4)]     = gch;   // g channel
    f4[idx4 + 2 * (HW / 4)] = bch;   // b channel
}

extern "C" void kernel_launch(void* const* d_in, const int* in_sizes, int n_in,
                              void* d_out, int out_size) {
    const float* init = (const float*)d_in[0];   // initial_state, 1024*1024 fp32
    float* out = (float*)d_out;                  // (T, 3, H, W) fp32

    const int n_frames = out_size / (3 * HW);

    const int threads = 256;
    const int blocks  = (HW / 4) / threads;      // 1024 blocks

    const float* src = init;
    for (int t = 0; t < n_frames; ++t) {
        float* frame = out + (size_t)t * 3 * HW;
        physics_step_kernel<<<blocks, threads>>>(src, frame);
        src = frame;  // r channel of frame t is u_{t+1}
    }
}

// round 2
// speedup vs baseline: 1.2464x; 1.2464x over previous
#include <cuda_runtime.h>
#include <cstdint>

// 64 steps of diffusion-advection on a 1024x1024 periodic grid, emitting
// (T, 3, H, W) fp32 RGB. r-channel of frame t == u_{t+1} exactly (clipped),
// so chunks chain through the r channel; no scratch state.
//
// Temporal blocking: T_STEPS=4 fused steps per kernel. Each block owns OHR=4
// rows, loads 12 full-width rows (+/-4 halo, periodic), runs 4 steps in
// double-buffered smem, writes 4 frames. x-neighbors via warp shuffle +
// warp-edge scalars from smem.

#define HH 1024
#define WW 1024
#define HW (HH * WW)

#define DT     0.1f
#define ALPHA  0.05f
#define V_X    0.1f
// V_Y == 0 -> du_dy term vanishes.

#define T_STEPS 4
#define OHR     4
#define RR      (OHR + 2 * T_STEPS)   // 12 rows per tile

extern __shared__ float sbuf[];       // 2 * RR * WW floats = 96 KB

__global__ __launch_bounds__(256, 2)
void physics_chunk_kernel(const float* __restrict__ u_in,
                          float* __restrict__ frames,   // base of frame t0
                          int steps)                    // 1..T_STEPS
{
    const int c4   = threadIdx.x;        // float4 column 0..255
    const int x0   = c4 << 2;
    const int lane = c4 & 31;
    const int y0   = blockIdx.x * OHR;   // owned rows y0..y0+OHR-1

    float* b0 = sbuf;
    float* b1 = sbuf + RR * WW;

    // Load RR rows (periodic halo) into buffer 0.
    const float4* in4 = (const float4*)u_in;
    #pragma unroll
    for (int rr = 0; rr < RR; ++rr) {
        const int gy = (y0 - T_STEPS + rr) & (HH - 1);
        ((float4*)b0)[rr * 256 + c4] = __ldcg(&in4[gy * 256 + c4]);
    }

    for (int s = 0; s < steps; ++s) {
        __syncthreads();   // covers initial load (s=0) and prior step's stores
        const float*  bo  = (s & 1) ? b1 : b0;
        float*        bn  = (s & 1) ? b0 : b1;
        const float4* bo4 = (const float4*)bo;
        float4*       bn4 = (float4*)bn;

        const int rlo = s + 1;
        const int rhi = RR - 2 - s;      // inclusive

        float4 up = bo4[(rlo - 1) * 256 + c4];
        float4 ce = bo4[rlo * 256 + c4];

        for (int r = rlo; r <= rhi; ++r) {
            float4 dn = bo4[(r + 1) * 256 + c4];

            // x-neighbors: shuffle across lanes, smem at warp edges
            float lw = __shfl_up_sync(0xffffffffu, ce.w, 1);
            float rx = __shfl_down_sync(0xffffffffu, ce.x, 1);
            if (lane == 0)  lw = bo[r * WW + ((x0 - 1) & (WW - 1))];
            if (lane == 31) rx = bo[r * WW + ((x0 + 4) & (WW - 1))];

            const float uc[4] = {ce.x, ce.y, ce.z, ce.w};
            const float ul[4] = {lw,   ce.x, ce.y, ce.z};
            const float ur[4] = {ce.y, ce.z, ce.w, rx};
            const float uu[4] = {up.x, up.y, up.z, up.w};
            const float ud[4] = {dn.x, dn.y, dn.z, dn.w};

            float4 un;
            float* unp = &un.x;
            #pragma unroll
            for (int i = 0; i < 4; ++i) {
                const float lap   = ul[i] + ur[i] + uu[i] + ud[i] - 4.0f * uc[i];
                const float du_dx = uc[i] - ul[i];
                float v = uc[i] + DT * (ALPHA * lap - V_X * du_dx);
                unp[i] = fminf(fmaxf(v, 0.0f), 1.0f);
            }

            bn4[r * 256 + c4] = un;

            // Frame output for owned rows
            if (r >= T_STEPS && r < T_STEPS + OHR) {
                const int gy  = y0 + (r - T_STEPS);
                const int idx = gy * 256 + c4;
                float4* f4 = (float4*)(frames + (size_t)s * 3 * HW);

                float4 gch, bch;
                gch.x = un.x * 0.5f; gch.y = un.y * 0.5f;
                gch.z = un.z * 0.5f; gch.w = un.w * 0.5f;
                bch.x = 1.0f - un.x; bch.y = 1.0f - un.y;
                bch.z = 1.0f - un.z; bch.w = 1.0f - un.w;

                // Only the last step's r channel is re-read (next chunk input);
                // everything else streams past L2.
                if (s == steps - 1) f4[idx] = un;
                else                __stcs(&f4[idx], un);
                __stcs(&f4[idx +     (HW / 4)], gch);
                __stcs(&f4[idx + 2 * (HW / 4)], bch);
            }

            up = ce;
            ce = dn;
        }
    }
}

extern "C" void kernel_launch(void* const* d_in, const int* in_sizes, int n_in,
                              void* d_out, int out_size) {
    const float* init = (const float*)d_in[0];
    float* out = (float*)d_out;

    const int n_frames = out_size / (3 * HW);
    const size_t shmem = (size_t)2 * RR * WW * sizeof(float);   // 98304 B

    cudaFuncSetAttribute(physics_chunk_kernel,
                         cudaFuncAttributeMaxDynamicSharedMemorySize,
                         (int)shmem);

    const float* src = init;
    for (int t0 = 0; t0 < n_frames; t0 += T_STEPS) {
        const int steps = (n_frames - t0 < T_STEPS) ? (n_frames - t0) : T_STEPS;
        float* fr = out + (size_t)t0 * 3 * HW;
        physics_chunk_kernel<<<HH / OHR, 256, shmem>>>(src, fr, steps);
        src = fr + (size_t)(steps - 1) * 3 * HW;   // r channel of last frame
    }
}